// round 9
// baseline (speedup 1.0000x reference)
#include <cuda_runtime.h>

// OWA pooling: 3x3 / stride 2 / pad(0,1,0,1) over (16,224,224,64) f32 NHWC.
// Per output element: descending-sort the 9 window values, dot with kernel[:,c].
//
// R8: occupancy push. One thread = one output pixel x 2 channels (single packed
// f32x2 chain, 9 u64 = 18 regs of sort state vs 36). Target 6 blocks/SM
// (48 warps, 75% occ) to hide DRAM latency; R7 showed issue=50% @ occ=41%
// with no pipe saturated (latency-bound).
//
// Compare-exchange (packed, hybrid):
//   s  = add.rn.f32x2(A, B)        (fma pipe)
//   hi = {max(al,bl), max(ah,bh)}  (2x FMNMX, alu pipe; exact)
//   A  = fma.rn.f32x2(hi, -1, s)   (fma pipe)  => lo, <=1 ulp-of-sum error

namespace {

constexpr int B_DIM = 16;
constexpr int H_IN = 224, W_IN = 224;
constexpr int H_OUT = 112, W_OUT = 112;
constexpr int C2 = 32;                               // 64 channels / 2 (u64 chunks)
constexpr int TOTAL2 = B_DIM * H_OUT * W_OUT * C2;   // 6,422,528 threads
constexpr int BLOCK = 256;                           // TOTAL2 % BLOCK == 0

constexpr unsigned long long NEG1X2 = 0xBF800000BF800000ULL;  // {-1.f, -1.f}

__device__ __forceinline__ void cash2(unsigned long long& A, unsigned long long& B) {
  asm("{\n\t"
      ".reg .f32 al, ah, bl, bh, hl, hh;\n\t"
      ".reg .b64 s64;\n\t"
      "add.rn.f32x2 s64, %0, %1;\n\t"
      "mov.b64 {al, ah}, %0;\n\t"
      "mov.b64 {bl, bh}, %1;\n\t"
      "max.f32 hl, al, bl;\n\t"
      "max.f32 hh, ah, bh;\n\t"
      "mov.b64 %1, {hl, hh};\n\t"
      "fma.rn.f32x2 %0, %1, %2, s64;\n\t"
      "}"
      : "+l"(A), "+l"(B)
      : "l"(NEG1X2));
}

__device__ __forceinline__ void fma2(unsigned long long& acc,
                                     unsigned long long v,
                                     unsigned long long w) {
  asm("fma.rn.f32x2 %0, %1, %2, %0;" : "+l"(acc) : "l"(v), "l"(w));
}

// Published optimal 9-element sorting network: 25 comparators, depth 7.
__device__ __forceinline__ void sort9p(unsigned long long (&v)[9]) {
  cash2(v[0],v[3]); cash2(v[1],v[7]); cash2(v[2],v[5]); cash2(v[4],v[8]);
  cash2(v[0],v[7]); cash2(v[2],v[4]); cash2(v[3],v[8]); cash2(v[5],v[6]);
  cash2(v[0],v[2]); cash2(v[1],v[3]); cash2(v[4],v[5]); cash2(v[7],v[8]);
  cash2(v[1],v[4]); cash2(v[3],v[6]); cash2(v[5],v[7]);
  cash2(v[0],v[1]); cash2(v[2],v[4]); cash2(v[3],v[5]); cash2(v[6],v[8]);
  cash2(v[2],v[3]); cash2(v[4],v[5]); cash2(v[6],v[7]);
  cash2(v[1],v[2]); cash2(v[3],v[4]); cash2(v[5],v[6]);
}

} // namespace

__global__ __launch_bounds__(BLOCK, 6)
void owa_pool_kernel(const unsigned long long* __restrict__ in2,
                     const unsigned long long* __restrict__ wk2,
                     unsigned long long* __restrict__ out2) {
  int tid = blockIdx.x * BLOCK + threadIdx.x;

  int c2  = tid & (C2 - 1);
  int pix = tid >> 5;
  int ow  = pix % W_OUT;
  int t   = pix / W_OUT;
  int oh  = t % H_OUT;
  int b   = t / H_OUT;

  int y0 = oh * 2;
  int x0 = ow * 2;

  unsigned long long v[9];
#pragma unroll
  for (int ky = 0; ky < 3; ++ky) {
    int y = y0 + ky;
    bool yok = (y < H_IN);
    int rowbase = (b * H_IN + y) * W_IN;
#pragma unroll
    for (int kx = 0; kx < 3; ++kx) {
      int x = x0 + kx;
      unsigned long long val = 0ULL;
      if (yok && x < W_IN) val = __ldg(&in2[(long)(rowbase + x) * C2 + c2]);
      v[ky * 3 + kx] = val;
    }
  }

  // Ascending sort; weight k applies to the k-th LARGEST -> pair v[i] with w[8-i].
  sort9p(v);

  unsigned long long acc = 0ULL;  // {0.f, 0.f}
  const unsigned long long* wkc = wk2 + c2;
#pragma unroll
  for (int k = 0; k < 9; ++k) {
    fma2(acc, v[k], __ldg(wkc + (8 - k) * C2));
  }

  out2[tid] = acc;
}

extern "C" void kernel_launch(void* const* d_in, const int* in_sizes, int n_in,
                              void* d_out, int out_size) {
  const unsigned long long* in2 = (const unsigned long long*)d_in[0];  // (16,224,224,64) f32
  const unsigned long long* wk2 = (const unsigned long long*)d_in[1];  // (9,64) f32
  unsigned long long* out2 = (unsigned long long*)d_out;               // (16,112,112,64) f32

  (void)in_sizes; (void)n_in; (void)out_size;
  int grid = TOTAL2 / BLOCK;
  owa_pool_kernel<<<grid, BLOCK>>>(in2, wk2, out2);
}